// round 11
// baseline (speedup 1.0000x reference)
#include <cuda_runtime.h>
#include <cuda_fp16.h>
#include <math.h>
#include <stdint.h>

#define TT    2048
#define DIMM  2048
#define NH    16
#define HD    128
#define EPSF  1.1920929e-07f

// ---------------- scratch (device globals: no allocation allowed) ----------
__device__ float g_q[TT * DIMM];
__device__ float g_k[TT * DIMM];
__device__ float g_v[TT * DIMM];
__device__ float g_cos[TT * 64];
__device__ float g_sin[TT * 64];

// fp16 operands (2-term split everywhere)
__device__ __half g_xfh[TT * DIMM],  g_xfl[TT * DIMM];
__device__ __half g_wqfh[DIMM * DIMM];
__device__ __half g_wkfh[DIMM * DIMM];
__device__ __half g_wvfh[DIMM * DIMM];
__device__ __half g_wpfh[DIMM * DIMM];
__device__ __half g_qfh[TT * DIMM],  g_qfl[TT * DIMM];
__device__ __half g_kfh[TT * DIMM];
__device__ __half g_vfh[TT * DIMM];
__device__ __half g_afh[TT * DIMM],  g_afl[TT * DIMM];

// ---------------- baseline-PTX helpers -------------------------------------
__device__ __forceinline__ uint32_t smem_u32(const void* p) {
    uint32_t a;
    asm("{ .reg .u64 t; cvta.to.shared.u64 t, %1; cvt.u32.u64 %0, t; }"
        : "=r"(a) : "l"(p));
    return a;
}
__device__ __forceinline__ void cp16(uint32_t dst, const void* src) {
    asm volatile("cp.async.cg.shared.global [%0], [%1], 16;"
                 :: "r"(dst), "l"(src) : "memory");
}
__device__ __forceinline__ void cp_commit() {
    asm volatile("cp.async.commit_group;" ::: "memory");
}
__device__ __forceinline__ void cp_wait1() {
    asm volatile("cp.async.wait_group 1;" ::: "memory");
}
__device__ __forceinline__ void cp_wait0() {
    asm volatile("cp.async.wait_group 0;" ::: "memory");
}

#define LDM_X4(r0, r1, r2, r3, a)                                              \
    asm volatile("ldmatrix.sync.aligned.m8n8.x4.shared.b16 {%0,%1,%2,%3},[%4];"\
                 : "=r"(r0), "=r"(r1), "=r"(r2), "=r"(r3) : "r"(a))
#define LDM_X4T(r0, r1, r2, r3, a)                                             \
    asm volatile(                                                              \
        "ldmatrix.sync.aligned.m8n8.x4.trans.shared.b16 {%0,%1,%2,%3},[%4];"   \
        : "=r"(r0), "=r"(r1), "=r"(r2), "=r"(r3) : "r"(a))

#define MMA_FP16(c, a, b)                                                      \
    asm volatile(                                                              \
        "mma.sync.aligned.m16n8k16.row.col.f32.f16.f16.f32 "                   \
        "{%0,%1,%2,%3},{%4,%5,%6,%7},{%8,%9},{%0,%1,%2,%3};"                   \
        : "+f"((c)[0]), "+f"((c)[1]), "+f"((c)[2]), "+f"((c)[3])               \
        : "r"((a)[0]), "r"((a)[1]), "r"((a)[2]), "r"((a)[3]),                  \
          "r"((b)[0]), "r"((b)[1]))

__device__ __forceinline__ uint32_t pack16(uint16_t a, uint16_t b) {
    return ((uint32_t)b << 16) | (uint32_t)a;
}
__device__ __forceinline__ void split2h(float a, float b, uint32_t& hi, uint32_t& lo) {
    __half ha = __float2half_rn(a), hb = __float2half_rn(b);
    __half la = __float2half_rn(a - __half2float(ha));
    __half lb = __float2half_rn(b - __half2float(hb));
    hi = pack16(*(uint16_t*)&ha, *(uint16_t*)&hb);
    lo = pack16(*(uint16_t*)&la, *(uint16_t*)&lb);
}

// ---------------- conversions (one grid, y selects tensor) -----------------
__global__ __launch_bounds__(256) void cvt_all(const float4* __restrict__ x,
                                               const float4* __restrict__ Wq,
                                               const float4* __restrict__ Wk,
                                               const float4* __restrict__ Wv,
                                               const float4* __restrict__ Wp) {
    int i = blockIdx.x * blockDim.x + threadIdx.x;
    if (i >= TT * DIMM / 4) return;
    const int y = blockIdx.y;
    if (y == 0) {
        float4 v = x[i];
        __half fh[4], fl[4];
#pragma unroll
        for (int e = 0; e < 4; e++) {
            float f = (&v.x)[e];
            fh[e] = __float2half_rn(f);
            fl[e] = __float2half_rn(f - __half2float(fh[e]));
        }
        ((uint2*)g_xfh)[i] = *(uint2*)fh;
        ((uint2*)g_xfl)[i] = *(uint2*)fl;
    } else {
        const float4* src = (y == 1) ? Wq : (y == 2) ? Wk : (y == 3) ? Wv : Wp;
        __half* hi = (y == 1) ? g_wqfh : (y == 2) ? g_wkfh
                   : (y == 3) ? g_wvfh : g_wpfh;
        float4 v = src[i];
        __half fh[4];
#pragma unroll
        for (int e = 0; e < 4; e++) fh[e] = __float2half_rn((&v.x)[e]);
        ((uint2*)hi)[i] = *(uint2*)fh;
    }
}

// ----- fp16 2-term GEMM: C = (Ah+Al) @ Bh^T, 8 warps of 32x64, K64 ---------
#define GROW   144
#define GTILE  (128 * GROW)        // 18432
#define GSTAGE (3 * GTILE)         // Ah, Al, Bh = 55296
#define GSMEM  (2 * GSTAGE)        // 110592 -> 2 CTAs/SM

__device__ __forceinline__ void g2_load_chunk(
    uint32_t base, const __half* Ah, const __half* Al, const __half* Bh,
    int mBase, int nBase, int kc, int tid) {
#pragma unroll
    for (int j = 0; j < 12; j++) {
        const int t = j >> 2;
        const int rem = tid + (j & 3) * 256;   // 0..1023
        const int r = rem >> 3;
        const int u = rem & 7;
        const __half* s = (t == 0) ? Ah : (t == 1) ? Al : Bh;
        const int rb = (t < 2) ? mBase : nBase;
        cp16(base + t * GTILE + r * GROW + u * 16,
             s + (size_t)(rb + r) * DIMM + kc + u * 8);
    }
}

__device__ __forceinline__ void gemm2_mma(const __half* Ah, const __half* Al,
                                          const __half* Bh, float* __restrict__ C) {
    extern __shared__ char sm[];
    const uint32_t smb = smem_u32(sm);
    const int tid = threadIdx.x;
    const int wid = tid >> 5;
    const int lane = tid & 31;
    const int mBase = blockIdx.y * 128;
    const int nBase = blockIdx.x * 128;
    const int wm = (wid >> 1) * 32;   // 4 m-slots of 32
    const int wn = (wid & 1) * 64;    // 2 n-slots of 64

    const int row16 = lane & 15;
    const int col16 = (lane >> 4) * 16;

    float acc[2][8][4];
#pragma unroll
    for (int i = 0; i < 2; i++)
#pragma unroll
        for (int n = 0; n < 8; n++)
#pragma unroll
            for (int v = 0; v < 4; v++) acc[i][n][v] = 0.0f;

    g2_load_chunk(smb, Ah, Al, Bh, mBase, nBase, 0, tid);
    cp_commit();

    for (int c = 0; c < 32; c++) {
        const uint32_t cur = smb + (c & 1) * GSTAGE;
        if (c + 1 < 32) {
            g2_load_chunk(smb + ((c + 1) & 1) * GSTAGE, Ah, Al, Bh,
                          mBase, nBase, (c + 1) * 64, tid);
            cp_commit();
            cp_wait1();
        } else {
            cp_wait0();
        }
        __syncthreads();

        const uint32_t Ab = cur;
        const uint32_t Alb = cur + GTILE;
        const uint32_t Bb = cur + 2 * GTILE;

#pragma unroll
        for (int s = 0; s < 4; s++) {
            uint32_t bh[8][2], af[2][4];
#pragma unroll
            for (int n2 = 0; n2 < 4; n2++) {
                uint32_t t0, t1, t2, t3;
                LDM_X4(t0, t1, t2, t3,
                       Bb + (wn + n2 * 16 + row16) * GROW + s * 32 + col16);
                bh[2 * n2][0] = t0; bh[2 * n2][1] = t2;
                bh[2 * n2 + 1][0] = t1; bh[2 * n2 + 1][1] = t3;
            }
#pragma unroll
            for (int i = 0; i < 2; i++)
                LDM_X4(af[i][0], af[i][1], af[i][2], af[i][3],
                       Ab + (wm + i * 16 + row16) * GROW + s * 32 + col16);
#pragma unroll
            for (int i = 0; i < 2; i++)
#pragma unroll
                for (int n = 0; n < 8; n++) MMA_FP16(acc[i][n], af[i], bh[n]);

#pragma unroll
            for (int i = 0; i < 2; i++)
                LDM_X4(af[i][0], af[i][1], af[i][2], af[i][3],
                       Alb + (wm + i * 16 + row16) * GROW + s * 32 + col16);
#pragma unroll
            for (int i = 0; i < 2; i++)
#pragma unroll
                for (int n = 0; n < 8; n++) MMA_FP16(acc[i][n], af[i], bh[n]);
        }
        __syncthreads();
    }

    const int r0 = mBase + wm + (lane >> 2);
    const int c0 = nBase + wn + (lane & 3) * 2;
#pragma unroll
    for (int i = 0; i < 2; i++)
#pragma unroll
        for (int n = 0; n < 8; n++) {
            *(float2*)&C[(size_t)(r0 + i * 16) * DIMM + c0 + n * 8] =
                make_float2(acc[i][n][0], acc[i][n][1]);
            *(float2*)&C[(size_t)(r0 + i * 16 + 8) * DIMM + c0 + n * 8] =
                make_float2(acc[i][n][2], acc[i][n][3]);
        }
}

__global__ __launch_bounds__(256, 2) void qkv_mma() {
    if (blockIdx.z == 0)      gemm2_mma(g_xfh, g_xfl, g_wqfh, g_q);
    else if (blockIdx.z == 1) gemm2_mma(g_xfh, g_xfl, g_wkfh, g_k);
    else                      gemm2_mma(g_xfh, g_xfl, g_wvfh, g_v);
}

__global__ __launch_bounds__(256, 2) void proj_mma(float* __restrict__ out) {
    gemm2_mma(g_afh, g_afl, g_wpfh, out);
}

// ---------------- RoPE cos/sin table ---------------------------------------
__global__ void rope_table() {
    int idx = blockIdx.x * blockDim.x + threadIdx.x;
    if (idx >= TT * 64) return;
    int t = idx >> 6;
    int i = idx & 63;
    float e = (float)(2 * i) * (1.0f / 128.0f);
    float invf = 1.0f / powf(10000.0f, e);
    float fr = (float)t * invf;
    g_cos[idx] = (float)cos((double)fr);
    g_sin[idx] = (float)sin((double)fr);
}

// ------- v-mix (-> fp16) + per-head RMS norm + RoPE (-> fp16 hi/lo) --------
__global__ __launch_bounds__(256) void post_qkv(const float* __restrict__ v1,
                                                const float* __restrict__ lambp) {
    const int t = blockIdx.x;
    const int tid = threadIdx.x;
    const float lamb = *lambp;

    const float* vrow = g_v + (size_t)t * DIMM;
    const float* v1row = v1 + (size_t)t * DIMM;
    uint32_t* vhp = (uint32_t*)g_vfh + (size_t)t * DIMM / 2;
    for (int i = tid; i < DIMM / 2; i += 256) {
        float a = (1.0f - lamb) * vrow[2 * i] + lamb * v1row[2 * i];
        float b = (1.0f - lamb) * vrow[2 * i + 1] + lamb * v1row[2 * i + 1];
        __half ha = __float2half_rn(a), hb = __float2half_rn(b);
        vhp[i] = pack16(*(uint16_t*)&ha, *(uint16_t*)&hb);
    }

    const int warp = tid >> 5;
    const int lane = tid & 31;

    for (int hh = warp; hh < 2 * NH; hh += 8) {
        const int head = hh >> 1;
        const int isK = hh & 1;
        const float* p = (isK ? g_k : g_q) + (size_t)t * DIMM + head * HD;
        uint32_t* dsth = (uint32_t*)(isK ? g_kfh : g_qfh) +
                         ((size_t)t * DIMM + head * HD) / 2;
        uint32_t* dstl = (uint32_t*)g_qfl + ((size_t)t * DIMM + head * HD) / 2;

        float4 f = *(const float4*)&p[lane * 4];
        float ss = f.x * f.x + f.y * f.y + f.z * f.z + f.w * f.w;
#pragma unroll
        for (int off = 16; off; off >>= 1) ss += __shfl_xor_sync(0xffffffffu, ss, off);
        float sc = rsqrtf(ss * (1.0f / 128.0f) + EPSF);
        __syncwarp();

        const int i0 = 2 * lane;
        float x1a = p[i0] * sc,     x2a = p[i0 + 64] * sc;
        float x1b = p[i0 + 1] * sc, x2b = p[i0 + 65] * sc;
        float ca = g_cos[t * 64 + i0], sa = g_sin[t * 64 + i0];
        float cb = g_cos[t * 64 + i0 + 1], sb = g_sin[t * 64 + i0 + 1];
        float y1a = x1a * ca + x2a * sa, y2a = x2a * ca - x1a * sa;
        float y1b = x1b * cb + x2b * sb, y2b = x2b * cb - x1b * sb;
        uint32_t hi, lo;
        split2h(y1a, y1b, hi, lo);
        dsth[lane] = hi;
        if (!isK) dstl[lane] = lo;
        split2h(y2a, y2b, hi, lo);
        dsth[lane + 32] = hi;
        if (!isK) dstl[lane + 32] = lo;
    }
}

// ---------------- flash attention (fp16 2-term S, fp16 2-term PV) ----------
#define FROW   272
#define FTILE  (64 * FROW)
#define FSTAGE (2 * FTILE)
#define FSMEM  (2 * FSTAGE)

__device__ __forceinline__ void f_load_stage(uint32_t base, int s0, int h, int tid) {
#pragma unroll
    for (int t = 0; t < 2; t++) {
        const __half* src = (t == 0) ? g_kfh : g_vfh;
#pragma unroll
        for (int j = 0; j < 4; j++) {
            int idx = tid + j * 256;
            int r = idx >> 4, u = idx & 15;
            cp16(base + t * FTILE + r * FROW + u * 16,
                 src + (size_t)(s0 + r) * DIMM + h * HD + u * 8);
        }
    }
}

__global__ __launch_bounds__(256, 1) void flash_mma() {
    extern __shared__ char sm[];
    const uint32_t smb = smem_u32(sm);
    const int h = blockIdx.y;
    const int qb = gridDim.x - 1 - blockIdx.x;
    const int q0 = qb * 128;
    const int tid = threadIdx.x;
    const int wid = tid >> 5;
    const int lane = tid & 31;
    const int wm = wid * 16;

    uint32_t qh[8][4], ql[8][4];
    {
        const uint32_t* qhp = (const uint32_t*)g_qfh;
        const uint32_t* qlp = (const uint32_t*)g_qfl;
        const int r0 = q0 + wm + (lane >> 2);
        const int cb = h * HD + (lane & 3) * 2;
#pragma unroll
        for (int ks = 0; ks < 8; ks++) {
            uint32_t i00 = ((uint32_t)r0 * DIMM + cb + ks * 16) >> 1;
            uint32_t i10 = i00 + 8 * (DIMM / 2);
            qh[ks][0] = qhp[i00];     qh[ks][1] = qhp[i10];
            qh[ks][2] = qhp[i00 + 4]; qh[ks][3] = qhp[i10 + 4];
            ql[ks][0] = qlp[i00];     ql[ks][1] = qlp[i10];
            ql[ks][2] = qlp[i00 + 4]; ql[ks][3] = qlp[i10 + 4];
        }
    }

    float o[16][4];
#pragma unroll
    for (int n = 0; n < 16; n++)
#pragma unroll
        for (int v = 0; v < 4; v++) o[n][v] = 0.0f;
    float m[2] = {-INFINITY, -INFINITY};
    float l[2] = {0.0f, 0.0f};

    const int nkb = 2 * qb + 2;
    const float scale2 = 0.08838834764831845f * 1.4426950408889634f;

    f_load_stage(smb, 0, h, tid);
    cp_commit();

    const int row16 = lane & 15;
    const int col16 = (lane >> 4) * 16;

    for (int kb = 0; kb < nkb; kb++) {
        const uint32_t cur = smb + (kb & 1) * FSTAGE;
        if (kb + 1 < nkb) {
            f_load_stage(smb + ((kb + 1) & 1) * FSTAGE, (kb + 1) * 64, h, tid);
            cp_commit();
            cp_wait1();
        } else {
            cp_wait0();
        }
        __syncthreads();

        const int s0 = kb * 64;
        const uint32_t Kh = cur;
        const uint32_t Vh = cur + FTILE;

        float sc_[8][4];
#pragma unroll
        for (int n = 0; n < 8; n++)
#pragma unroll
            for (int v = 0; v < 4; v++) sc_[n][v] = 0.0f;

#pragma unroll
        for (int ks = 0; ks < 8; ks++) {
#pragma unroll
            for (int np = 0; np < 4; np++) {
                uint32_t bh[2][2];
                uint32_t t0, t1, t2, t3;
                LDM_X4(t0, t1, t2, t3,
                       Kh + (np * 16 + row16) * FROW + ks * 32 + col16);
                bh[0][0] = t0; bh[0][1] = t2; bh[1][0] = t1; bh[1][1] = t3;
                MMA_FP16(sc_[2 * np], qh[ks], bh[0]);
                MMA_FP16(sc_[2 * np], ql[ks], bh[0]);
                MMA_FP16(sc_[2 * np + 1], qh[ks], bh[1]);
                MMA_FP16(sc_[2 * np + 1], ql[ks], bh[1]);
            }
        }

        if (s0 + 63 > q0 + wm) {
            const int r0 = q0 + wm + (lane >> 2);
#pragma unroll
            for (int n = 0; n < 8; n++) {
                int c0 = s0 + n * 8 + (lane & 3) * 2;
#pragma unroll
                for (int e = 0; e < 2; e++) {
                    sc_[n][e]     = (c0 + e <= r0)     ? sc_[n][e] * scale2     : -1e30f;
                    sc_[n][e + 2] = (c0 + e <= r0 + 8) ? sc_[n][e + 2] * scale2 : -1e30f;
                }
            }
        } else {
#pragma unroll
            for (int n = 0; n < 8; n++)
#pragma unroll
                for (int v = 0; v < 4; v++) sc_[n][v] *= scale2;
        }

        float alpha[2];
#pragma unroll
        for (int e = 0; e < 2; e++) {
            float mt = m[e];
#pragma unroll
            for (int n = 0; n < 8; n++)
                mt = fmaxf(mt, fmaxf(sc_[n][2 * e], sc_[n][2 * e + 1]));
            mt = fmaxf(mt, __shfl_xor_sync(0xffffffffu, mt, 1));
            mt = fmaxf(mt, __shfl_xor_sync(0xffffffffu, mt, 2));
            alpha[e] = exp2f(m[e] - mt);
            m[e] = mt;
            float sum = 0.0f;
#pragma unroll
            for (int n = 0; n < 8; n++) {
                float p0 = exp2f(sc_[n][2 * e] - mt);
                float p1 = exp2f(sc_[n][2 * e + 1] - mt);
                sc_[n][2 * e] = p0;
                sc_[n][2 * e + 1] = p1;
                sum += p0 + p1;
            }
            sum += __shfl_xor_sync(0xffffffffu, sum, 1);
            sum += __shfl_xor_sync(0xffffffffu, sum, 2);
            l[e] = l[e] * alpha[e] + sum;
        }
#pragma unroll
        for (int n = 0; n < 16; n++) {
            o[n][0] *= alpha[0];
            o[n][1] *= alpha[0];
            o[n][2] *= alpha[1];
            o[n][3] *= alpha[1];
        }

        uint32_t ph[4][4], pl[4][4];
#pragma unroll
        for (int ks = 0; ks < 4; ks++) {
            split2h(sc_[2 * ks][0],     sc_[2 * ks][1],     ph[ks][0], pl[ks][0]);
            split2h(sc_[2 * ks][2],     sc_[2 * ks][3],     ph[ks][1], pl[ks][1]);
            split2h(sc_[2 * ks + 1][0], sc_[2 * ks + 1][1], ph[ks][2], pl[ks][2]);
            split2h(sc_[2 * ks + 1][2], sc_[2 * ks + 1][3], ph[ks][3], pl[ks][3]);
        }

#pragma unroll
        for (int ks = 0; ks < 4; ks++) {
#pragma unroll
            for (int np = 0; np < 8; np++) {
                uint32_t v2[2][2];
                uint32_t t0, t1, t2, t3;
                LDM_X4T(t0, t1, t2, t3,
                        Vh + (ks * 16 + row16) * FROW + np * 32 + col16);
                v2[0][0] = t0; v2[0][1] = t1; v2[1][0] = t2; v2[1][1] = t3;
                MMA_FP16(o[2 * np], ph[ks], v2[0]);
                MMA_FP16(o[2 * np], pl[ks], v2[0]);
                MMA_FP16(o[2 * np + 1], ph[ks], v2[1]);
                MMA_FP16(o[2 * np + 1], pl[ks], v2[1]);
            }
        }
        __syncthreads();
    }

    const float linv0 = 1.0f / l[0];
    const float linv1 = 1.0f / l[1];
    uint32_t* ahp = (uint32_t*)g_afh;
    uint32_t* alp = (uint32_t*)g_afl;
    const int r0 = q0 + wm + (lane >> 2);
    const int cb = h * HD + (lane & 3) * 2;
#pragma unroll
    for (int n = 0; n < 16; n++) {
        uint32_t i0 = ((uint32_t)r0 * DIMM + cb + n * 8) >> 1;
        uint32_t i1 = i0 + 8 * (DIMM / 2);
        uint32_t hi, lo;
        split2h(o[n][0] * linv0, o[n][1] * linv0, hi, lo);
        ahp[i0] = hi; alp[i0] = lo;
        split2h(o[n][2] * linv1, o[n][3] * linv1, hi, lo);
        ahp[i1] = hi; alp[i1] = lo;
    }
}

// ---------------- v1 passthrough -------------------------------------------
__global__ void copy_v1(const float4* __restrict__ src, float4* __restrict__ dst, int n4) {
    int idx = blockIdx.x * blockDim.x + threadIdx.x;
    if (idx < n4) dst[idx] = src[idx];
}

// ---------------- launch ----------------------------------------------------
extern "C" void kernel_launch(void* const* d_in, const int* in_sizes, int n_in,
                              void* d_out, int out_size) {
    const float* x = (const float*)d_in[0];
    const float* v1 = (const float*)d_in[1];
    const float* Wq = (const float*)d_in[2];
    const float* Wk = (const float*)d_in[3];
    const float* Wv = (const float*)d_in[4];
    const float* Wp = (const float*)d_in[5];
    const float* lamb = (const float*)d_in[6];
    float* out = (float*)d_out;

    cudaFuncSetAttribute(qkv_mma, cudaFuncAttributeMaxDynamicSharedMemorySize, GSMEM);
    cudaFuncSetAttribute(proj_mma, cudaFuncAttributeMaxDynamicSharedMemorySize, GSMEM);
    cudaFuncSetAttribute(flash_mma, cudaFuncAttributeMaxDynamicSharedMemorySize, FSMEM);

    rope_table<<<(TT * 64 + 255) / 256, 256>>>();

    const int n4 = TT * DIMM / 4;
    dim3 gcvt((n4 + 255) / 256, 5);
    cvt_all<<<gcvt, 256>>>((const float4*)x, (const float4*)Wq, (const float4*)Wk,
                           (const float4*)Wv, (const float4*)Wp);

    if (out_size >= 2 * TT * DIMM) {
        copy_v1<<<(TT * DIMM / 4 + 255) / 256, 256>>>(
            (const float4*)v1, (float4*)(out + (size_t)TT * DIMM), TT * DIMM / 4);
    }

    dim3 gqkv(DIMM / 128, TT / 128, 3);
    qkv_mma<<<gqkv, 256, GSMEM>>>();

    post_qkv<<<TT, 256>>>(v1, lamb);

    dim3 gfl(TT / 128, NH);
    flash_mma<<<gfl, 256, FSMEM>>>();

    dim3 gproj(DIMM / 128, TT / 128);
    proj_mma<<<gproj, 256, GSMEM>>>(out);
}

// round 12
// speedup vs baseline: 1.7037x; 1.7037x over previous
#include <cuda_runtime.h>
#include <cuda_fp16.h>
#include <math.h>
#include <stdint.h>

#define TT    2048
#define DIMM  2048
#define NH    16
#define HD    128
#define EPSF  1.1920929e-07f

// ---------------- scratch (device globals: no allocation allowed) ----------
__device__ float g_q[TT * DIMM];
__device__ float g_k[TT * DIMM];
__device__ float g_v[TT * DIMM];
__device__ float g_cos[TT * 64];
__device__ float g_sin[TT * 64];

// fp16 operands (single-term everywhere)
__device__ __half g_xfh[TT * DIMM];
__device__ __half g_wqfh[DIMM * DIMM];
__device__ __half g_wkfh[DIMM * DIMM];
__device__ __half g_wvfh[DIMM * DIMM];
__device__ __half g_wpfh[DIMM * DIMM];
__device__ __half g_qfh[TT * DIMM];
__device__ __half g_kfh[TT * DIMM];
__device__ __half g_vfh[TT * DIMM];
__device__ __half g_afh[TT * DIMM];

// ---------------- baseline-PTX helpers -------------------------------------
__device__ __forceinline__ uint32_t smem_u32(const void* p) {
    uint32_t a;
    asm("{ .reg .u64 t; cvta.to.shared.u64 t, %1; cvt.u32.u64 %0, t; }"
        : "=r"(a) : "l"(p));
    return a;
}
__device__ __forceinline__ void cp16(uint32_t dst, const void* src) {
    asm volatile("cp.async.cg.shared.global [%0], [%1], 16;"
                 :: "r"(dst), "l"(src) : "memory");
}
__device__ __forceinline__ void cp_commit() {
    asm volatile("cp.async.commit_group;" ::: "memory");
}
__device__ __forceinline__ void cp_wait1() {
    asm volatile("cp.async.wait_group 1;" ::: "memory");
}
__device__ __forceinline__ void cp_wait0() {
    asm volatile("cp.async.wait_group 0;" ::: "memory");
}

#define LDM_X4(r0, r1, r2, r3, a)                                              \
    asm volatile("ldmatrix.sync.aligned.m8n8.x4.shared.b16 {%0,%1,%2,%3},[%4];"\
                 : "=r"(r0), "=r"(r1), "=r"(r2), "=r"(r3) : "r"(a))
#define LDM_X4T(r0, r1, r2, r3, a)                                             \
    asm volatile(                                                              \
        "ldmatrix.sync.aligned.m8n8.x4.trans.shared.b16 {%0,%1,%2,%3},[%4];"   \
        : "=r"(r0), "=r"(r1), "=r"(r2), "=r"(r3) : "r"(a))

#define MMA_FP16(c, a, b)                                                      \
    asm volatile(                                                              \
        "mma.sync.aligned.m16n8k16.row.col.f32.f16.f16.f32 "                   \
        "{%0,%1,%2,%3},{%4,%5,%6,%7},{%8,%9},{%0,%1,%2,%3};"                   \
        : "+f"((c)[0]), "+f"((c)[1]), "+f"((c)[2]), "+f"((c)[3])               \
        : "r"((a)[0]), "r"((a)[1]), "r"((a)[2]), "r"((a)[3]),                  \
          "r"((b)[0]), "r"((b)[1]))

__device__ __forceinline__ uint32_t pack16(uint16_t a, uint16_t b) {
    return ((uint32_t)b << 16) | (uint32_t)a;
}
__device__ __forceinline__ uint32_t f2x_h(float a, float b) {
    __half2 h = __floats2half2_rn(a, b);
    return *(uint32_t*)&h;
}

// ---------------- conversions (one grid, y selects tensor) -----------------
__global__ __launch_bounds__(256) void cvt_all(const float4* __restrict__ x,
                                               const float4* __restrict__ Wq,
                                               const float4* __restrict__ Wk,
                                               const float4* __restrict__ Wv,
                                               const float4* __restrict__ Wp) {
    int i = blockIdx.x * blockDim.x + threadIdx.x;
    if (i >= TT * DIMM / 4) return;
    const int y = blockIdx.y;
    const float4* src = (y == 0) ? x : (y == 1) ? Wq : (y == 2) ? Wk
                      : (y == 3) ? Wv : Wp;
    __half* dst = (y == 0) ? g_xfh : (y == 1) ? g_wqfh : (y == 2) ? g_wkfh
                : (y == 3) ? g_wvfh : g_wpfh;
    float4 v = src[i];
    __half fh[4];
#pragma unroll
    for (int e = 0; e < 4; e++) fh[e] = __float2half_rn((&v.x)[e]);
    ((uint2*)dst)[i] = *(uint2*)fh;
}

// ----- fp16 GEMM: C = A @ B^T, 8 warps of 32x64, K-chunk 64 ----------------
#define GROW   144
#define GTILE  (128 * GROW)        // 18432
#define GSTAGE (2 * GTILE)         // A, B = 36864
#define GSMEM  (2 * GSTAGE)        // 73728

__device__ __forceinline__ void g1_load_chunk(
    uint32_t base, const __half* A, const __half* B,
    int mBase, int nBase, int kc, int tid) {
#pragma unroll
    for (int j = 0; j < 8; j++) {
        const int t = j >> 2;
        const int rem = tid + (j & 3) * 256;   // 0..1023
        const int r = rem >> 3;
        const int u = rem & 7;
        const __half* s = (t == 0) ? A : B;
        const int rb = (t == 0) ? mBase : nBase;
        cp16(base + t * GTILE + r * GROW + u * 16,
             s + (size_t)(rb + r) * DIMM + kc + u * 8);
    }
}

__device__ __forceinline__ void gemm1_mma(const __half* A, const __half* B,
                                          float* __restrict__ C) {
    extern __shared__ char sm[];
    const uint32_t smb = smem_u32(sm);
    const int tid = threadIdx.x;
    const int wid = tid >> 5;
    const int lane = tid & 31;
    const int mBase = blockIdx.y * 128;
    const int nBase = blockIdx.x * 128;
    const int wm = (wid >> 1) * 32;
    const int wn = (wid & 1) * 64;

    const int row16 = lane & 15;
    const int col16 = (lane >> 4) * 16;

    float acc[2][8][4];
#pragma unroll
    for (int i = 0; i < 2; i++)
#pragma unroll
        for (int n = 0; n < 8; n++)
#pragma unroll
            for (int v = 0; v < 4; v++) acc[i][n][v] = 0.0f;

    g1_load_chunk(smb, A, B, mBase, nBase, 0, tid);
    cp_commit();

    for (int c = 0; c < 32; c++) {
        const uint32_t cur = smb + (c & 1) * GSTAGE;
        if (c + 1 < 32) {
            g1_load_chunk(smb + ((c + 1) & 1) * GSTAGE, A, B,
                          mBase, nBase, (c + 1) * 64, tid);
            cp_commit();
            cp_wait1();
        } else {
            cp_wait0();
        }
        __syncthreads();

        const uint32_t Ab = cur;
        const uint32_t Bb = cur + GTILE;

#pragma unroll
        for (int s = 0; s < 4; s++) {
            uint32_t bh[8][2], af[2][4];
#pragma unroll
            for (int n2 = 0; n2 < 4; n2++) {
                uint32_t t0, t1, t2, t3;
                LDM_X4(t0, t1, t2, t3,
                       Bb + (wn + n2 * 16 + row16) * GROW + s * 32 + col16);
                bh[2 * n2][0] = t0; bh[2 * n2][1] = t2;
                bh[2 * n2 + 1][0] = t1; bh[2 * n2 + 1][1] = t3;
            }
#pragma unroll
            for (int i = 0; i < 2; i++)
                LDM_X4(af[i][0], af[i][1], af[i][2], af[i][3],
                       Ab + (wm + i * 16 + row16) * GROW + s * 32 + col16);
#pragma unroll
            for (int i = 0; i < 2; i++)
#pragma unroll
                for (int n = 0; n < 8; n++) MMA_FP16(acc[i][n], af[i], bh[n]);
        }
        __syncthreads();
    }

    const int r0 = mBase + wm + (lane >> 2);
    const int c0 = nBase + wn + (lane & 3) * 2;
#pragma unroll
    for (int i = 0; i < 2; i++)
#pragma unroll
        for (int n = 0; n < 8; n++) {
            *(float2*)&C[(size_t)(r0 + i * 16) * DIMM + c0 + n * 8] =
                make_float2(acc[i][n][0], acc[i][n][1]);
            *(float2*)&C[(size_t)(r0 + i * 16 + 8) * DIMM + c0 + n * 8] =
                make_float2(acc[i][n][2], acc[i][n][3]);
        }
}

__global__ __launch_bounds__(256, 2) void qkv_mma() {
    if (blockIdx.z == 0)      gemm1_mma(g_xfh, g_wqfh, g_q);
    else if (blockIdx.z == 1) gemm1_mma(g_xfh, g_wkfh, g_k);
    else                      gemm1_mma(g_xfh, g_wvfh, g_v);
}

__global__ __launch_bounds__(256, 2) void proj_mma(float* __restrict__ out) {
    gemm1_mma(g_afh, g_wpfh, out);
}

// ---------------- RoPE cos/sin table ---------------------------------------
__global__ void rope_table() {
    int idx = blockIdx.x * blockDim.x + threadIdx.x;
    if (idx >= TT * 64) return;
    int t = idx >> 6;
    int i = idx & 63;
    float e = (float)(2 * i) * (1.0f / 128.0f);
    float invf = 1.0f / powf(10000.0f, e);
    float fr = (float)t * invf;
    g_cos[idx] = (float)cos((double)fr);
    g_sin[idx] = (float)sin((double)fr);
}

// ------- v-mix (-> fp16) + per-head RMS norm + RoPE (-> fp16) --------------
__global__ __launch_bounds__(256) void post_qkv(const float* __restrict__ v1,
                                                const float* __restrict__ lambp) {
    const int t = blockIdx.x;
    const int tid = threadIdx.x;
    const float lamb = *lambp;

    const float* vrow = g_v + (size_t)t * DIMM;
    const float* v1row = v1 + (size_t)t * DIMM;
    uint32_t* vhp = (uint32_t*)g_vfh + (size_t)t * DIMM / 2;
    for (int i = tid; i < DIMM / 2; i += 256) {
        float a = (1.0f - lamb) * vrow[2 * i] + lamb * v1row[2 * i];
        float b = (1.0f - lamb) * vrow[2 * i + 1] + lamb * v1row[2 * i + 1];
        vhp[i] = f2x_h(a, b);
    }

    const int warp = tid >> 5;
    const int lane = tid & 31;

    for (int hh = warp; hh < 2 * NH; hh += 8) {
        const int head = hh >> 1;
        const int isK = hh & 1;
        const float* p = (isK ? g_k : g_q) + (size_t)t * DIMM + head * HD;
        uint32_t* dsth = (uint32_t*)(isK ? g_kfh : g_qfh) +
                         ((size_t)t * DIMM + head * HD) / 2;

        float4 f = *(const float4*)&p[lane * 4];
        float ss = f.x * f.x + f.y * f.y + f.z * f.z + f.w * f.w;
#pragma unroll
        for (int off = 16; off; off >>= 1) ss += __shfl_xor_sync(0xffffffffu, ss, off);
        float sc = rsqrtf(ss * (1.0f / 128.0f) + EPSF);
        __syncwarp();

        const int i0 = 2 * lane;
        float x1a = p[i0] * sc,     x2a = p[i0 + 64] * sc;
        float x1b = p[i0 + 1] * sc, x2b = p[i0 + 65] * sc;
        float ca = g_cos[t * 64 + i0], sa = g_sin[t * 64 + i0];
        float cb = g_cos[t * 64 + i0 + 1], sb = g_sin[t * 64 + i0 + 1];
        float y1a = x1a * ca + x2a * sa, y2a = x2a * ca - x1a * sa;
        float y1b = x1b * cb + x2b * sb, y2b = x2b * cb - x1b * sb;
        dsth[lane] = f2x_h(y1a, y1b);
        dsth[lane + 32] = f2x_h(y2a, y2b);
    }
}

// ---------------- flash attention (fp16 single-term S and PV) --------------
#define FROW   272
#define FTILE  (64 * FROW)
#define FSTAGE (2 * FTILE)
#define FSMEM  (2 * FSTAGE)

__device__ __forceinline__ void f_load_stage(uint32_t base, int s0, int h, int tid) {
#pragma unroll
    for (int t = 0; t < 2; t++) {
        const __half* src = (t == 0) ? g_kfh : g_vfh;
#pragma unroll
        for (int j = 0; j < 4; j++) {
            int idx = tid + j * 256;
            int r = idx >> 4, u = idx & 15;
            cp16(base + t * FTILE + r * FROW + u * 16,
                 src + (size_t)(s0 + r) * DIMM + h * HD + u * 8);
        }
    }
}

__global__ __launch_bounds__(256, 1) void flash_mma() {
    extern __shared__ char sm[];
    const uint32_t smb = smem_u32(sm);
    const int h = blockIdx.y;
    const int qb = gridDim.x - 1 - blockIdx.x;
    const int q0 = qb * 128;
    const int tid = threadIdx.x;
    const int wid = tid >> 5;
    const int lane = tid & 31;
    const int wm = wid * 16;

    uint32_t qh[8][4];
    {
        const uint32_t* qhp = (const uint32_t*)g_qfh;
        const int r0 = q0 + wm + (lane >> 2);
        const int cb = h * HD + (lane & 3) * 2;
#pragma unroll
        for (int ks = 0; ks < 8; ks++) {
            uint32_t i00 = ((uint32_t)r0 * DIMM + cb + ks * 16) >> 1;
            uint32_t i10 = i00 + 8 * (DIMM / 2);
            qh[ks][0] = qhp[i00];     qh[ks][1] = qhp[i10];
            qh[ks][2] = qhp[i00 + 4]; qh[ks][3] = qhp[i10 + 4];
        }
    }

    float o[16][4];
#pragma unroll
    for (int n = 0; n < 16; n++)
#pragma unroll
        for (int v = 0; v < 4; v++) o[n][v] = 0.0f;
    float m[2] = {-INFINITY, -INFINITY};
    float l[2] = {0.0f, 0.0f};

    const int nkb = 2 * qb + 2;
    const float scale2 = 0.08838834764831845f * 1.4426950408889634f;

    f_load_stage(smb, 0, h, tid);
    cp_commit();

    const int row16 = lane & 15;
    const int col16 = (lane >> 4) * 16;

    for (int kb = 0; kb < nkb; kb++) {
        const uint32_t cur = smb + (kb & 1) * FSTAGE;
        if (kb + 1 < nkb) {
            f_load_stage(smb + ((kb + 1) & 1) * FSTAGE, (kb + 1) * 64, h, tid);
            cp_commit();
            cp_wait1();
        } else {
            cp_wait0();
        }
        __syncthreads();

        const int s0 = kb * 64;
        const uint32_t Kh = cur;
        const uint32_t Vh = cur + FTILE;

        float sc_[8][4];
#pragma unroll
        for (int n = 0; n < 8; n++)
#pragma unroll
            for (int v = 0; v < 4; v++) sc_[n][v] = 0.0f;

#pragma unroll
        for (int ks = 0; ks < 8; ks++) {
#pragma unroll
            for (int np = 0; np < 4; np++) {
                uint32_t bh[2][2];
                uint32_t t0, t1, t2, t3;
                LDM_X4(t0, t1, t2, t3,
                       Kh + (np * 16 + row16) * FROW + ks * 32 + col16);
                bh[0][0] = t0; bh[0][1] = t2; bh[1][0] = t1; bh[1][1] = t3;
                MMA_FP16(sc_[2 * np], qh[ks], bh[0]);
                MMA_FP16(sc_[2 * np + 1], qh[ks], bh[1]);
            }
        }

        if (s0 + 63 > q0 + wm) {
            const int r0 = q0 + wm + (lane >> 2);
#pragma unroll
            for (int n = 0; n < 8; n++) {
                int c0 = s0 + n * 8 + (lane & 3) * 2;
#pragma unroll
                for (int e = 0; e < 2; e++) {
                    sc_[n][e]     = (c0 + e <= r0)     ? sc_[n][e] * scale2     : -1e30f;
                    sc_[n][e + 2] = (c0 + e <= r0 + 8) ? sc_[n][e + 2] * scale2 : -1e30f;
                }
            }
        } else {
#pragma unroll
            for (int n = 0; n < 8; n++)
#pragma unroll
                for (int v = 0; v < 4; v++) sc_[n][v] *= scale2;
        }

        float alpha[2];
#pragma unroll
        for (int e = 0; e < 2; e++) {
            float mt = m[e];
#pragma unroll
            for (int n = 0; n < 8; n++)
                mt = fmaxf(mt, fmaxf(sc_[n][2 * e], sc_[n][2 * e + 1]));
            mt = fmaxf(mt, __shfl_xor_sync(0xffffffffu, mt, 1));
            mt = fmaxf(mt, __shfl_xor_sync(0xffffffffu, mt, 2));
            alpha[e] = exp2f(m[e] - mt);
            m[e] = mt;
            float sum = 0.0f;
#pragma unroll
            for (int n = 0; n < 8; n++) {
                float p0 = exp2f(sc_[n][2 * e] - mt);
                float p1 = exp2f(sc_[n][2 * e + 1] - mt);
                sc_[n][2 * e] = p0;
                sc_[n][2 * e + 1] = p1;
                sum += p0 + p1;
            }
            sum += __shfl_xor_sync(0xffffffffu, sum, 1);
            sum += __shfl_xor_sync(0xffffffffu, sum, 2);
            l[e] = l[e] * alpha[e] + sum;
        }
#pragma unroll
        for (int n = 0; n < 16; n++) {
            o[n][0] *= alpha[0];
            o[n][1] *= alpha[0];
            o[n][2] *= alpha[1];
            o[n][3] *= alpha[1];
        }

        // P -> fp16 A-fragments (single term)
        uint32_t ph[4][4];
#pragma unroll
        for (int ks = 0; ks < 4; ks++) {
            ph[ks][0] = f2x_h(sc_[2 * ks][0],     sc_[2 * ks][1]);
            ph[ks][1] = f2x_h(sc_[2 * ks][2],     sc_[2 * ks][3]);
            ph[ks][2] = f2x_h(sc_[2 * ks + 1][0], sc_[2 * ks + 1][1]);
            ph[ks][3] = f2x_h(sc_[2 * ks + 1][2], sc_[2 * ks + 1][3]);
        }

#pragma unroll
        for (int ks = 0; ks < 4; ks++) {
#pragma unroll
            for (int np = 0; np < 8; np++) {
                uint32_t v2[2][2];
                uint32_t t0, t1, t2, t3;
                LDM_X4T(t0, t1, t2, t3,
                        Vh + (ks * 16 + row16) * FROW + np * 32 + col16);
                v2[0][0] = t0; v2[0][1] = t1; v2[1][0] = t2; v2[1][1] = t3;
                MMA_FP16(o[2 * np], ph[ks], v2[0]);
                MMA_FP16(o[2 * np + 1], ph[ks], v2[1]);
            }
        }
        __syncthreads();
    }

    const float linv0 = 1.0f / l[0];
    const float linv1 = 1.0f / l[1];
    uint32_t* ahp = (uint32_t*)g_afh;
    const int r0 = q0 + wm + (lane >> 2);
    const int cb = h * HD + (lane & 3) * 2;
#pragma unroll
    for (int n = 0; n < 16; n++) {
        uint32_t i0 = ((uint32_t)r0 * DIMM + cb + n * 8) >> 1;
        uint32_t i1 = i0 + 8 * (DIMM / 2);
        ahp[i0] = f2x_h(o[n][0] * linv0, o[n][1] * linv0);
        ahp[i1] = f2x_h(o[n][2] * linv1, o[n][3] * linv1);
    }
}

// ---------------- v1 passthrough -------------------------------------------
__global__ void copy_v1(const float4* __restrict__ src, float4* __restrict__ dst, int n4) {
    int idx = blockIdx.x * blockDim.x + threadIdx.x;
    if (idx < n4) dst[idx] = src[idx];
}

// ---------------- launch ----------------------------------------------------
extern "C" void kernel_launch(void* const* d_in, const int* in_sizes, int n_in,
                              void* d_out, int out_size) {
    const float* x = (const float*)d_in[0];
    const float* v1 = (const float*)d_in[1];
    const float* Wq = (const float*)d_in[2];
    const float* Wk = (const float*)d_in[3];
    const float* Wv = (const float*)d_in[4];
    const float* Wp = (const float*)d_in[5];
    const float* lamb = (const float*)d_in[6];
    float* out = (float*)d_out;

    cudaFuncSetAttribute(qkv_mma, cudaFuncAttributeMaxDynamicSharedMemorySize, GSMEM);
    cudaFuncSetAttribute(proj_mma, cudaFuncAttributeMaxDynamicSharedMemorySize, GSMEM);
    cudaFuncSetAttribute(flash_mma, cudaFuncAttributeMaxDynamicSharedMemorySize, FSMEM);

    rope_table<<<(TT * 64 + 255) / 256, 256>>>();

    const int n4 = TT * DIMM / 4;
    dim3 gcvt((n4 + 255) / 256, 5);
    cvt_all<<<gcvt, 256>>>((const float4*)x, (const float4*)Wq, (const float4*)Wk,
                           (const float4*)Wv, (const float4*)Wp);

    if (out_size >= 2 * TT * DIMM) {
        copy_v1<<<(TT * DIMM / 4 + 255) / 256, 256>>>(
            (const float4*)v1, (float4*)(out + (size_t)TT * DIMM), TT * DIMM / 4);
    }

    dim3 gqkv(DIMM / 128, TT / 128, 3);
    qkv_mma<<<gqkv, 256, GSMEM>>>();

    post_qkv<<<TT, 256>>>(v1, lamb);

    dim3 gfl(TT / 128, NH);
    flash_mma<<<gfl, 256, FSMEM>>>();

    dim3 gproj(DIMM / 128, TT / 128);
    proj_mma<<<gproj, 256, GSMEM>>>(out);
}

// round 14
// speedup vs baseline: 1.9227x; 1.1285x over previous
#include <cuda_runtime.h>
#include <cuda_fp16.h>
#include <math.h>
#include <stdint.h>

#define TT    2048
#define DIMM  2048
#define NH    16
#define HD    128
#define EPSF  1.1920929e-07f

// ---------------- scratch (device globals: no allocation allowed) ----------
__device__ float g_q[TT * DIMM];
__device__ float g_k[TT * DIMM];
__device__ float g_v[TT * DIMM];
__device__ float g_cos[TT * 64];
__device__ float g_sin[TT * 64];

// fp16 operands (single-term everywhere)
__device__ __half g_xfh[TT * DIMM];
__device__ __half g_wqfh[DIMM * DIMM];
__device__ __half g_wkfh[DIMM * DIMM];
__device__ __half g_wvfh[DIMM * DIMM];
__device__ __half g_wpfh[DIMM * DIMM];
__device__ __half g_qfh[TT * DIMM];
__device__ __half g_kfh[TT * DIMM];
__device__ __half g_vfh[TT * DIMM];
__device__ __half g_afh[TT * DIMM];

// ---------------- baseline-PTX helpers -------------------------------------
__device__ __forceinline__ uint32_t smem_u32(const void* p) {
    uint32_t a;
    asm("{ .reg .u64 t; cvta.to.shared.u64 t, %1; cvt.u32.u64 %0, t; }"
        : "=r"(a) : "l"(p));
    return a;
}
__device__ __forceinline__ void cp16(uint32_t dst, const void* src) {
    asm volatile("cp.async.cg.shared.global [%0], [%1], 16;"
                 :: "r"(dst), "l"(src) : "memory");
}
__device__ __forceinline__ void cp_commit() {
    asm volatile("cp.async.commit_group;" ::: "memory");
}
__device__ __forceinline__ void cp_wait1() {
    asm volatile("cp.async.wait_group 1;" ::: "memory");
}
__device__ __forceinline__ void cp_wait0() {
    asm volatile("cp.async.wait_group 0;" ::: "memory");
}

#define LDM_X4(r0, r1, r2, r3, a)                                              \
    asm volatile("ldmatrix.sync.aligned.m8n8.x4.shared.b16 {%0,%1,%2,%3},[%4];"\
                 : "=r"(r0), "=r"(r1), "=r"(r2), "=r"(r3) : "r"(a))
#define LDM_X4T(r0, r1, r2, r3, a)                                             \
    asm volatile(                                                              \
        "ldmatrix.sync.aligned.m8n8.x4.trans.shared.b16 {%0,%1,%2,%3},[%4];"   \
        : "=r"(r0), "=r"(r1), "=r"(r2), "=r"(r3) : "r"(a))

#define MMA_FP16(c, a, b)                                                      \
    asm volatile(                                                              \
        "mma.sync.aligned.m16n8k16.row.col.f32.f16.f16.f32 "                   \
        "{%0,%1,%2,%3},{%4,%5,%6,%7},{%8,%9},{%0,%1,%2,%3};"                   \
        : "+f"((c)[0]), "+f"((c)[1]), "+f"((c)[2]), "+f"((c)[3])               \
        : "r"((a)[0]), "r"((a)[1]), "r"((a)[2]), "r"((a)[3]),                  \
          "r"((b)[0]), "r"((b)[1]))

__device__ __forceinline__ uint32_t f2x_h(float a, float b) {
    __half2 h = __floats2half2_rn(a, b);
    return *(uint32_t*)&h;
}

// ---------------- conversions: 4 independent float4 per thread (MLP=4) -----
__global__ __launch_bounds__(256) void cvt_all(const float4* __restrict__ x,
                                               const float4* __restrict__ Wq,
                                               const float4* __restrict__ Wk,
                                               const float4* __restrict__ Wv,
                                               const float4* __restrict__ Wp) {
    const int y = blockIdx.y;
    const float4* src = (y == 0) ? x : (y == 1) ? Wq : (y == 2) ? Wk
                      : (y == 3) ? Wv : Wp;
    __half* dst = (y == 0) ? g_xfh : (y == 1) ? g_wqfh : (y == 2) ? g_wkfh
                : (y == 3) ? g_wvfh : g_wpfh;
    const int base = blockIdx.x * 1024 + threadIdx.x;
    float4 v[4];
#pragma unroll
    for (int e = 0; e < 4; e++) v[e] = src[base + e * 256];
#pragma unroll
    for (int e = 0; e < 4; e++) {
        __half fh[4];
        fh[0] = __float2half_rn(v[e].x);
        fh[1] = __float2half_rn(v[e].y);
        fh[2] = __float2half_rn(v[e].z);
        fh[3] = __float2half_rn(v[e].w);
        ((uint2*)dst)[base + e * 256] = *(uint2*)fh;
    }
}

// ----- fp16 GEMM: C = A @ B^T, 8 warps of 32x64, K-chunk 64 ----------------
#define GROW   144
#define GTILE  (128 * GROW)        // 18432
#define GSTAGE (2 * GTILE)         // A, B = 36864
#define GSMEM  (2 * GSTAGE)        // 73728

__device__ __forceinline__ void g1_load_chunk(
    uint32_t base, const __half* A, const __half* B,
    int mBase, int nBase, int kc, int tid) {
#pragma unroll
    for (int j = 0; j < 8; j++) {
        const int t = j >> 2;
        const int rem = tid + (j & 3) * 256;   // 0..1023
        const int r = rem >> 3;
        const int u = rem & 7;
        const __half* s = (t == 0) ? A : B;
        const int rb = (t == 0) ? mBase : nBase;
        cp16(base + t * GTILE + r * GROW + u * 16,
             s + (size_t)(rb + r) * DIMM + kc + u * 8);
    }
}

__device__ __forceinline__ void gemm1_mma(const __half* A, const __half* B,
                                          float* __restrict__ C) {
    extern __shared__ char sm[];
    const uint32_t smb = smem_u32(sm);
    const int tid = threadIdx.x;
    const int wid = tid >> 5;
    const int lane = tid & 31;
    const int mBase = blockIdx.y * 128;
    const int nBase = blockIdx.x * 128;
    const int wm = (wid >> 1) * 32;
    const int wn = (wid & 1) * 64;

    const int row16 = lane & 15;
    const int col16 = (lane >> 4) * 16;

    float acc[2][8][4];
#pragma unroll
    for (int i = 0; i < 2; i++)
#pragma unroll
        for (int n = 0; n < 8; n++)
#pragma unroll
            for (int v = 0; v < 4; v++) acc[i][n][v] = 0.0f;

    g1_load_chunk(smb, A, B, mBase, nBase, 0, tid);
    cp_commit();

    for (int c = 0; c < 32; c++) {
        const uint32_t cur = smb + (c & 1) * GSTAGE;
        if (c + 1 < 32) {
            g1_load_chunk(smb + ((c + 1) & 1) * GSTAGE, A, B,
                          mBase, nBase, (c + 1) * 64, tid);
            cp_commit();
            cp_wait1();
        } else {
            cp_wait0();
        }
        __syncthreads();

        const uint32_t Ab = cur;
        const uint32_t Bb = cur + GTILE;

#pragma unroll
        for (int s = 0; s < 4; s++) {
            uint32_t bh[8][2], af[2][4];
#pragma unroll
            for (int n2 = 0; n2 < 4; n2++) {
                uint32_t t0, t1, t2, t3;
                LDM_X4(t0, t1, t2, t3,
                       Bb + (wn + n2 * 16 + row16) * GROW + s * 32 + col16);
                bh[2 * n2][0] = t0; bh[2 * n2][1] = t2;
                bh[2 * n2 + 1][0] = t1; bh[2 * n2 + 1][1] = t3;
            }
#pragma unroll
            for (int i = 0; i < 2; i++)
                LDM_X4(af[i][0], af[i][1], af[i][2], af[i][3],
                       Ab + (wm + i * 16 + row16) * GROW + s * 32 + col16);
#pragma unroll
            for (int i = 0; i < 2; i++)
#pragma unroll
                for (int n = 0; n < 8; n++) MMA_FP16(acc[i][n], af[i], bh[n]);
        }
        __syncthreads();
    }

    const int r0 = mBase + wm + (lane >> 2);
    const int c0 = nBase + wn + (lane & 3) * 2;
#pragma unroll
    for (int i = 0; i < 2; i++)
#pragma unroll
        for (int n = 0; n < 8; n++) {
            *(float2*)&C[(size_t)(r0 + i * 16) * DIMM + c0 + n * 8] =
                make_float2(acc[i][n][0], acc[i][n][1]);
            *(float2*)&C[(size_t)(r0 + i * 16 + 8) * DIMM + c0 + n * 8] =
                make_float2(acc[i][n][2], acc[i][n][3]);
        }
}

__global__ __launch_bounds__(256, 2) void qkv_mma() {
    if (blockIdx.z == 0)      gemm1_mma(g_xfh, g_wqfh, g_q);
    else if (blockIdx.z == 1) gemm1_mma(g_xfh, g_wkfh, g_k);
    else                      gemm1_mma(g_xfh, g_wvfh, g_v);
}

__global__ __launch_bounds__(256, 2) void proj_mma(float* __restrict__ out) {
    gemm1_mma(g_afh, g_wpfh, out);
}

// ---------------- RoPE cos/sin table (all-f32, matches ref precision) ------
__global__ void rope_table() {
    int idx = blockIdx.x * blockDim.x + threadIdx.x;
    if (idx >= TT * 64) return;
    int t = idx >> 6;
    int i = idx & 63;
    float e = (float)(2 * i) * (1.0f / 128.0f);
    float invf = 1.0f / powf(10000.0f, e);
    float fr = (float)t * invf;
    g_cos[idx] = cosf(fr);
    g_sin[idx] = sinf(fr);
}

// ------- v-mix (-> fp16) + per-head RMS norm + RoPE (-> fp16) --------------
__global__ __launch_bounds__(256) void post_qkv(const float* __restrict__ v1,
                                                const float* __restrict__ lambp) {
    const int t = blockIdx.x;
    const int tid = threadIdx.x;
    const float lamb = *lambp;

    const float* vrow = g_v + (size_t)t * DIMM;
    const float* v1row = v1 + (size_t)t * DIMM;
    uint32_t* vhp = (uint32_t*)g_vfh + (size_t)t * DIMM / 2;
    for (int i = tid; i < DIMM / 2; i += 256) {
        float a = (1.0f - lamb) * vrow[2 * i] + lamb * v1row[2 * i];
        float b = (1.0f - lamb) * vrow[2 * i + 1] + lamb * v1row[2 * i + 1];
        vhp[i] = f2x_h(a, b);
    }

    const int warp = tid >> 5;
    const int lane = tid & 31;

    for (int hh = warp; hh < 2 * NH; hh += 8) {
        const int head = hh >> 1;
        const int isK = hh & 1;
        const float* p = (isK ? g_k : g_q) + (size_t)t * DIMM + head * HD;
        uint32_t* dsth = (uint32_t*)(isK ? g_kfh : g_qfh) +
                         ((size_t)t * DIMM + head * HD) / 2;

        float4 f = *(const float4*)&p[lane * 4];
        float ss = f.x * f.x + f.y * f.y + f.z * f.z + f.w * f.w;
#pragma unroll
        for (int off = 16; off; off >>= 1) ss += __shfl_xor_sync(0xffffffffu, ss, off);
        float sc = rsqrtf(ss * (1.0f / 128.0f) + EPSF);
        __syncwarp();

        const int i0 = 2 * lane;
        float x1a = p[i0] * sc,     x2a = p[i0 + 64] * sc;
        float x1b = p[i0 + 1] * sc, x2b = p[i0 + 65] * sc;
        float ca = g_cos[t * 64 + i0], sa = g_sin[t * 64 + i0];
        float cb = g_cos[t * 64 + i0 + 1], sb = g_sin[t * 64 + i0 + 1];
        float y1a = x1a * ca + x2a * sa, y2a = x2a * ca - x1a * sa;
        float y1b = x1b * cb + x2b * sb, y2b = x2b * cb - x1b * sb;
        dsth[lane] = f2x_h(y1a, y1b);
        dsth[lane + 32] = f2x_h(y2a, y2b);
    }
}

// ---------------- flash attention: paired q-tiles, 128 CTAs, one wave ------
#define FROW   272
#define FTILE  (64 * FROW)
#define FSTAGE (2 * FTILE)
#define FSMEM  (2 * FSTAGE)

__device__ __forceinline__ void f_load_stage(uint32_t base, int s0, int h, int tid) {
#pragma unroll
    for (int t = 0; t < 2; t++) {
        const __half* src = (t == 0) ? g_kfh : g_vfh;
#pragma unroll
        for (int j = 0; j < 4; j++) {
            int idx = tid + j * 256;
            int r = idx >> 4, u = idx & 15;
            cp16(base + t * FTILE + r * FROW + u * 16,
                 src + (size_t)(s0 + r) * DIMM + h * HD + u * 8);
        }
    }
}

__global__ __launch_bounds__(256, 1) void flash_mma() {
    extern __shared__ char sm[];
    const uint32_t smb = smem_u32(sm);
    const int h = blockIdx.y;
    const int tid = threadIdx.x;
    const int wid = tid >> 5;
    const int lane = tid & 31;
    const int wm = wid * 16;

    const int row16 = lane & 15;
    const int col16 = (lane >> 4) * 16;
    const float scale2 = 0.08838834764831845f * 1.4426950408889634f;
    const int NTILES = TT / 128;  // 16

#pragma unroll 1
    for (int half = 0; half < 2; half++) {
        const int qb = half ? (NTILES - 1 - (int)blockIdx.x) : (int)blockIdx.x;
        const int q0 = qb * 128;
        const int nkb = 2 * qb + 2;

        // ---- Q fragments ----
        uint32_t qh[8][4];
        {
            const uint32_t* qhp = (const uint32_t*)g_qfh;
            const int r0 = q0 + wm + (lane >> 2);
            const int cb = h * HD + (lane & 3) * 2;
#pragma unroll
            for (int ks = 0; ks < 8; ks++) {
                uint32_t i00 = ((uint32_t)r0 * DIMM + cb + ks * 16) >> 1;
                uint32_t i10 = i00 + 8 * (DIMM / 2);
                qh[ks][0] = qhp[i00];     qh[ks][1] = qhp[i10];
                qh[ks][2] = qhp[i00 + 4]; qh[ks][3] = qhp[i10 + 4];
            }
        }

        float o[16][4];
#pragma unroll
        for (int n = 0; n < 16; n++)
#pragma unroll
            for (int v = 0; v < 4; v++) o[n][v] = 0.0f;
        float m[2] = {-INFINITY, -INFINITY};
        float l[2] = {0.0f, 0.0f};

        f_load_stage(smb, 0, h, tid);
        cp_commit();

        for (int kb = 0; kb < nkb; kb++) {
            const uint32_t cur = smb + (kb & 1) * FSTAGE;
            if (kb + 1 < nkb) {
                f_load_stage(smb + ((kb + 1) & 1) * FSTAGE, (kb + 1) * 64, h, tid);
                cp_commit();
                cp_wait1();
            } else {
                cp_wait0();
            }
            __syncthreads();

            const int s0 = kb * 64;
            const uint32_t Kh = cur;
            const uint32_t Vh = cur + FTILE;

            float sc_[8][4];
#pragma unroll
            for (int n = 0; n < 8; n++)
#pragma unroll
                for (int v = 0; v < 4; v++) sc_[n][v] = 0.0f;

#pragma unroll
            for (int ks = 0; ks < 8; ks++) {
#pragma unroll
                for (int np = 0; np < 4; np++) {
                    uint32_t bh[2][2];
                    uint32_t t0, t1, t2, t3;
                    LDM_X4(t0, t1, t2, t3,
                           Kh + (np * 16 + row16) * FROW + ks * 32 + col16);
                    bh[0][0] = t0; bh[0][1] = t2; bh[1][0] = t1; bh[1][1] = t3;
                    MMA_FP16(sc_[2 * np], qh[ks], bh[0]);
                    MMA_FP16(sc_[2 * np + 1], qh[ks], bh[1]);
                }
            }

            if (s0 + 63 > q0 + wm) {
                const int r0 = q0 + wm + (lane >> 2);
#pragma unroll
                for (int n = 0; n < 8; n++) {
                    int c0 = s0 + n * 8 + (lane & 3) * 2;
#pragma unroll
                    for (int e = 0; e < 2; e++) {
                        sc_[n][e]     = (c0 + e <= r0)     ? sc_[n][e] * scale2     : -1e30f;
                        sc_[n][e + 2] = (c0 + e <= r0 + 8) ? sc_[n][e + 2] * scale2 : -1e30f;
                    }
                }
            } else {
#pragma unroll
                for (int n = 0; n < 8; n++)
#pragma unroll
                    for (int v = 0; v < 4; v++) sc_[n][v] *= scale2;
            }

            float alpha[2];
#pragma unroll
            for (int e = 0; e < 2; e++) {
                float mt = m[e];
#pragma unroll
                for (int n = 0; n < 8; n++)
                    mt = fmaxf(mt, fmaxf(sc_[n][2 * e], sc_[n][2 * e + 1]));
                mt = fmaxf(mt, __shfl_xor_sync(0xffffffffu, mt, 1));
                mt = fmaxf(mt, __shfl_xor_sync(0xffffffffu, mt, 2));
                alpha[e] = exp2f(m[e] - mt);
                m[e] = mt;
                float sum = 0.0f;
#pragma unroll
                for (int n = 0; n < 8; n++) {
                    float p0 = exp2f(sc_[n][2 * e] - mt);
                    float p1 = exp2f(sc_[n][2 * e + 1] - mt);
                    sc_[n][2 * e] = p0;
                    sc_[n][2 * e + 1] = p1;
                    sum += p0 + p1;
                }
                sum += __shfl_xor_sync(0xffffffffu, sum, 1);
                sum += __shfl_xor_sync(0xffffffffu, sum, 2);
                l[e] = l[e] * alpha[e] + sum;
            }
#pragma unroll
            for (int n = 0; n < 16; n++) {
                o[n][0] *= alpha[0];
                o[n][1] *= alpha[0];
                o[n][2] *= alpha[1];
                o[n][3] *= alpha[1];
            }

            uint32_t ph[4][4];
#pragma unroll
            for (int ks = 0; ks < 4; ks++) {
                ph[ks][0] = f2x_h(sc_[2 * ks][0],     sc_[2 * ks][1]);
                ph[ks][1] = f2x_h(sc_[2 * ks][2],     sc_[2 * ks][3]);
                ph[ks][2] = f2x_h(sc_[2 * ks + 1][0], sc_[2 * ks + 1][1]);
                ph[ks][3] = f2x_h(sc_[2 * ks + 1][2], sc_[2 * ks + 1][3]);
            }

#pragma unroll
            for (int ks = 0; ks < 4; ks++) {
#pragma unroll
                for (int np = 0; np < 8; np++) {
                    uint32_t v2[2][2];
                    uint32_t t0, t1, t2, t3;
                    LDM_X4T(t0, t1, t2, t3,
                            Vh + (ks * 16 + row16) * FROW + np * 32 + col16);
                    v2[0][0] = t0; v2[0][1] = t1; v2[1][0] = t2; v2[1][1] = t3;
                    MMA_FP16(o[2 * np], ph[ks], v2[0]);
                    MMA_FP16(o[2 * np + 1], ph[ks], v2[1]);
                }
            }
            __syncthreads();
        }

        const float linv0 = 1.0f / l[0];
        const float linv1 = 1.0f / l[1];
        uint32_t* ahp = (uint32_t*)g_afh;
        const int r0 = q0 + wm + (lane >> 2);
        const int cb = h * HD + (lane & 3) * 2;
#pragma unroll
        for (int n = 0; n < 16; n++) {
            uint32_t i0 = ((uint32_t)r0 * DIMM + cb + n * 8) >> 1;
            uint32_t i1 = i0 + 8 * (DIMM / 2);
            ahp[i0] = f2x_h(o[n][0] * linv0, o[n][1] * linv0);
            ahp[i1] = f2x_h(o[n][2] * linv1, o[n][3] * linv1);
        }
        __syncthreads();
    }
}

// ---------------- v1 passthrough (MLP=4) -----------------------------------
__global__ __launch_bounds__(256) void copy_v1(const float4* __restrict__ src,
                                               float4* __restrict__ dst) {
    const int base = blockIdx.x * 1024 + threadIdx.x;
    float4 v[4];
#pragma unroll
    for (int e = 0; e < 4; e++) v[e] = src[base + e * 256];
#pragma unroll
    for (int e = 0; e < 4; e++) dst[base + e * 256] = v[e];
}

// ---------------- launch ----------------------------------------------------
extern "C" void kernel_launch(void* const* d_in, const int* in_sizes, int n_in,
                              void* d_out, int out_size) {
    const float* x = (const float*)d_in[0];
    const float* v1 = (const float*)d_in[1];
    const float* Wq = (const float*)d_in[2];
    const float* Wk = (const float*)d_in[3];
    const float* Wv = (const float*)d_in[4];
    const float* Wp = (const float*)d_in[5];
    const float* lamb = (const float*)d_in[6];
    float* out = (float*)d_out;

    cudaFuncSetAttribute(qkv_mma, cudaFuncAttributeMaxDynamicSharedMemorySize, GSMEM);
    cudaFuncSetAttribute(proj_mma, cudaFuncAttributeMaxDynamicSharedMemorySize, GSMEM);
    cudaFuncSetAttribute(flash_mma, cudaFuncAttributeMaxDynamicSharedMemorySize, FSMEM);

    rope_table<<<(TT * 64 + 255) / 256, 256>>>();

    const int n4 = TT * DIMM / 4;          // 1048576 float4s
    dim3 gcvt(n4 / 1024, 5);
    cvt_all<<<gcvt, 256>>>((const float4*)x, (const float4*)Wq, (const float4*)Wk,
                           (const float4*)Wv, (const float4*)Wp);

    if (out_size >= 2 * TT * DIMM) {
        copy_v1<<<n4 / 1024, 256>>>((const float4*)v1,
                                    (float4*)(out + (size_t)TT * DIMM));
    }

    dim3 gqkv(DIMM / 128, TT / 128, 3);
    qkv_mma<<<gqkv, 256, GSMEM>>>();

    post_qkv<<<TT, 256>>>(v1, lamb);

    dim3 gfl(TT / 256, NH);                // 8 x 16 = 128 CTAs (paired tiles)
    flash_mma<<<gfl, 256, FSMEM>>>();

    dim3 gproj(DIMM / 128, TT / 128);
    proj_mma<<<gproj, 256, GSMEM>>>(out);
}